// round 4
// baseline (speedup 1.0000x reference)
#include <cuda_runtime.h>
#include <cuda_bf16.h>

#define N_NODES 50000
#define N_EDGES 800000
#define IN_DIM 128
#define HID_DIM 128
#define N_CLASSES 64

// ---------------- scratch: natively-typed __device__ globals ----------------
__device__ float4 g_hs1[N_NODES * 32];  // (x@W1)*dinv[row], 128 floats/row = 32 float4
__device__ float4 g_h1 [N_NODES * 32];  // relu(agg1)
__device__ float2 g_hs2[N_NODES * 32];  // (h1@W2)*dinv[row], 64 floats/row = 32 float2
__device__ int    g_counts[N_NODES];
__device__ int    g_cursor[N_NODES];
__device__ int    g_rowstart[N_NODES + 1];
__device__ int    g_blocksums[128];
__device__ int    g_csr[N_EDGES];
__device__ float  g_dinv[N_NODES];

// ---------------- CSR build ----------------
__global__ void k_init_counts() {
    int i = blockIdx.x * blockDim.x + threadIdx.x;
    if (i < N_NODES) { g_counts[i] = 0; g_cursor[i] = 0; }
}

// edge_index is int32 [2, N_EDGES]: row 0 = src, row 1 = dst
__global__ void k_hist(const int* __restrict__ dst) {
    int e = blockIdx.x * blockDim.x + threadIdx.x;
    if (e < N_EDGES) {
        int d = dst[e];
        if (d >= 0 && d < N_NODES) atomicAdd(&g_counts[d], 1);
    }
}

// 2-level exclusive scan of g_counts -> g_rowstart (512-thread blocks)
__global__ void k_scan_block() {
    __shared__ int s[512];
    int tid = threadIdx.x;
    int gid = blockIdx.x * 512 + tid;
    int v = (gid < N_NODES) ? g_counts[gid] : 0;
    s[tid] = v;
    __syncthreads();
    for (int off = 1; off < 512; off <<= 1) {
        int t = 0;
        if (tid >= off) t = s[tid - off];
        __syncthreads();
        if (tid >= off) s[tid] += t;
        __syncthreads();
    }
    if (gid < N_NODES) g_rowstart[gid] = s[tid] - v;  // exclusive
    if (tid == 511) g_blocksums[blockIdx.x] = s[511];
}

__global__ void k_scan_sums(int nb) {
    int acc = 0;
    for (int i = 0; i < nb; i++) { int t = g_blocksums[i]; g_blocksums[i] = acc; acc += t; }
}

__global__ void k_scan_add() {
    int tid = threadIdx.x;
    int gid = blockIdx.x * 512 + tid;
    if (gid < N_NODES) g_rowstart[gid] += g_blocksums[blockIdx.x];
    if (blockIdx.x == 0 && tid == 0) g_rowstart[N_NODES] = N_EDGES;
}

__global__ void k_dinv() {
    int i = blockIdx.x * blockDim.x + threadIdx.x;
    if (i < N_NODES) {
        float deg = (float)(g_counts[i] + 1);  // + self loop, always >= 1
        g_dinv[i] = rsqrtf(deg);
    }
}

__global__ void k_fill(const int* __restrict__ src, const int* __restrict__ dst) {
    int e = blockIdx.x * blockDim.x + threadIdx.x;
    if (e < N_EDGES) {
        int d = dst[e];
        int sv = src[e];
        if (d >= 0 && d < N_NODES && sv >= 0 && sv < N_NODES) {
            int pos = g_rowstart[d] + atomicAdd(&g_cursor[d], 1);
            if (pos >= 0 && pos < N_EDGES) g_csr[pos] = sv;
        }
    }
}

// ---------------- GEMM layer 1: g_hs1[r] = (x[r] @ W1) * dinv[r] ----------------
// Block = 64 rows x 128 cols, 256 threads. K-chunked KC=32.
// row_local = tid & 63 -> warp lanes share cg => Ws4 reads broadcast;
// Xs reads stride-33 -> conflict-free.
__global__ __launch_bounds__(256) void k_gemm1(const float* __restrict__ X,
                                               const float* __restrict__ W) {
    __shared__ float4 Ws4[32 * 32];     // 32 k-rows x 128 cols = 1024 float4
    __shared__ float  Xs[64][33];
    const int tid = threadIdx.x;
    const int row0 = blockIdx.x * 64;
    const int row_local = tid & 63;
    const int cg = tid >> 6;            // 0..3, 32 cols each

    float acc[32];
#pragma unroll
    for (int j = 0; j < 32; j++) acc[j] = 0.f;

    for (int kc0 = 0; kc0 < 128; kc0 += 32) {
        for (int i = tid; i < 1024; i += 256)
            Ws4[i] = ((const float4*)(W + kc0 * 128))[i];
        for (int i = tid; i < 512; i += 256) {
            int r = i >> 3, q = i & 7;
            int gr = row0 + r;
            float4 v = make_float4(0.f, 0.f, 0.f, 0.f);
            if (gr < N_NODES) v = ((const float4*)(X + gr * 128 + kc0))[q];
            Xs[r][q * 4 + 0] = v.x; Xs[r][q * 4 + 1] = v.y;
            Xs[r][q * 4 + 2] = v.z; Xs[r][q * 4 + 3] = v.w;
        }
        __syncthreads();

#pragma unroll 4
        for (int kk = 0; kk < 32; kk++) {
            float xv = Xs[row_local][kk];
            int base = kk * 32 + cg * 8;
#pragma unroll
            for (int j = 0; j < 8; j++) {
                float4 w = Ws4[base + j];
                acc[4 * j + 0] += xv * w.x;
                acc[4 * j + 1] += xv * w.y;
                acc[4 * j + 2] += xv * w.z;
                acc[4 * j + 3] += xv * w.w;
            }
        }
        __syncthreads();
    }

    int gr = row0 + row_local;
    if (gr < N_NODES) {
        float d = g_dinv[gr];
#pragma unroll
        for (int j = 0; j < 8; j++)
            g_hs1[gr * 32 + cg * 8 + j] =
                make_float4(acc[4 * j] * d, acc[4 * j + 1] * d,
                            acc[4 * j + 2] * d, acc[4 * j + 3] * d);
    }
}

// ---------------- GEMM layer 2: g_hs2[r] = (g_h1[r] @ W2) * dinv[r] ----------------
__global__ __launch_bounds__(256) void k_gemm2(const float* __restrict__ W) {
    __shared__ float4 Ws4[32 * 16];     // 32 k-rows x 64 cols = 512 float4
    __shared__ float  Xs[64][33];
    const int tid = threadIdx.x;
    const int row0 = blockIdx.x * 64;
    const int row_local = tid & 63;
    const int cg = tid >> 6;            // 0..3, 16 cols each

    float acc[16];
#pragma unroll
    for (int j = 0; j < 16; j++) acc[j] = 0.f;

    for (int kc0 = 0; kc0 < 128; kc0 += 32) {
        for (int i = tid; i < 512; i += 256)
            Ws4[i] = ((const float4*)(W + kc0 * 64))[i];
        for (int i = tid; i < 512; i += 256) {
            int r = i >> 3, q = i & 7;
            int gr = row0 + r;
            float4 v = make_float4(0.f, 0.f, 0.f, 0.f);
            if (gr < N_NODES) v = g_h1[gr * 32 + (kc0 >> 2) + q];
            Xs[r][q * 4 + 0] = v.x; Xs[r][q * 4 + 1] = v.y;
            Xs[r][q * 4 + 2] = v.z; Xs[r][q * 4 + 3] = v.w;
        }
        __syncthreads();

#pragma unroll 4
        for (int kk = 0; kk < 32; kk++) {
            float xv = Xs[row_local][kk];
            int base = kk * 16 + cg * 4;
#pragma unroll
            for (int j = 0; j < 4; j++) {
                float4 w = Ws4[base + j];
                acc[4 * j + 0] += xv * w.x;
                acc[4 * j + 1] += xv * w.y;
                acc[4 * j + 2] += xv * w.z;
                acc[4 * j + 3] += xv * w.w;
            }
        }
        __syncthreads();
    }

    int gr = row0 + row_local;
    if (gr < N_NODES) {
        float d = g_dinv[gr];
#pragma unroll
        for (int j = 0; j < 8; j++)
            g_hs2[gr * 32 + cg * 8 + j] =
                make_float2(acc[2 * j] * d, acc[2 * j + 1] * d);
    }
}

// ---------------- aggregation layer 1: warp per node, shared index staging ----------------
// g_h1[node] = relu( (g_hs1[node] + sum_src g_hs1[src]) * dinv[node] + b1 )
__global__ __launch_bounds__(256) void k_agg1(const float* __restrict__ bias) {
    __shared__ int sidx[8][32];
    int node = (blockIdx.x * blockDim.x + threadIdx.x) >> 5;
    if (node >= N_NODES) return;
    int w = threadIdx.x >> 5;
    int lane = threadIdx.x & 31;

    int s = g_rowstart[node];
    int e = g_rowstart[node + 1];
    float d = g_dinv[node];

    float4 a = g_hs1[node * 32 + lane];  // self loop
    for (int base = s; base < e; base += 32) {
        int idx = base + lane;
        sidx[w][lane] = (idx < e) ? g_csr[idx] : 0;
        __syncwarp();
        int cnt = min(32, e - base);
        for (int j = 0; j < cnt; j++) {
            float4 v = g_hs1[sidx[w][j] * 32 + lane];
            a.x += v.x; a.y += v.y; a.z += v.z; a.w += v.w;
        }
        __syncwarp();
    }
    float bx = bias[lane * 4 + 0], by = bias[lane * 4 + 1];
    float bz = bias[lane * 4 + 2], bw = bias[lane * 4 + 3];
    g_h1[node * 32 + lane] = make_float4(
        fmaxf(a.x * d + bx, 0.f), fmaxf(a.y * d + by, 0.f),
        fmaxf(a.z * d + bz, 0.f), fmaxf(a.w * d + bw, 0.f));
}

// ---------------- aggregation layer 2: writes harness output ----------------
__global__ __launch_bounds__(256) void k_agg2(const float* __restrict__ bias,
                                              float* __restrict__ out) {
    __shared__ int sidx[8][32];
    int node = (blockIdx.x * blockDim.x + threadIdx.x) >> 5;
    if (node >= N_NODES) return;
    int w = threadIdx.x >> 5;
    int lane = threadIdx.x & 31;

    int s = g_rowstart[node];
    int e = g_rowstart[node + 1];
    float d = g_dinv[node];

    float2 a = g_hs2[node * 32 + lane];  // self loop
    for (int base = s; base < e; base += 32) {
        int idx = base + lane;
        sidx[w][lane] = (idx < e) ? g_csr[idx] : 0;
        __syncwarp();
        int cnt = min(32, e - base);
        for (int j = 0; j < cnt; j++) {
            float2 v = g_hs2[sidx[w][j] * 32 + lane];
            a.x += v.x; a.y += v.y;
        }
        __syncwarp();
    }
    float bx = bias[lane * 2 + 0], by = bias[lane * 2 + 1];
    out[node * 64 + lane * 2 + 0] = a.x * d + bx;
    out[node * 64 + lane * 2 + 1] = a.y * d + by;
}

// ---------------- launch: kernel launches ONLY ----------------
extern "C" void kernel_launch(void* const* d_in, const int* in_sizes, int n_in,
                              void* d_out, int out_size) {
    const float* x = (const float*)d_in[0];
    const int* ei = (const int*)d_in[1];   // int32 [2, N_EDGES]
    const float* W1 = (const float*)d_in[2];
    const float* b1 = (const float*)d_in[3];
    const float* W2 = (const float*)d_in[4];
    const float* b2 = (const float*)d_in[5];
    float* out = (float*)d_out;

    const int* esrc = ei;
    const int* edst = ei + N_EDGES;

    const int NB_SCAN = (N_NODES + 511) / 512;  // 98

    // CSR build + degrees
    k_init_counts<<<(N_NODES + 255) / 256, 256>>>();
    k_hist<<<(N_EDGES + 255) / 256, 256>>>(edst);
    k_scan_block<<<NB_SCAN, 512>>>();
    k_scan_sums<<<1, 1>>>(NB_SCAN);
    k_scan_add<<<NB_SCAN, 512>>>();
    k_dinv<<<(N_NODES + 255) / 256, 256>>>();
    k_fill<<<(N_EDGES + 255) / 256, 256>>>(esrc, edst);

    const int gemm_blocks = (N_NODES + 63) / 64;        // 782
    const int agg_blocks = (N_NODES + 7) / 8;           // 6250 (8 warps/block)

    // layer 1
    k_gemm1<<<gemm_blocks, 256>>>(x, W1);
    k_agg1<<<agg_blocks, 256>>>(b1);
    // layer 2
    k_gemm2<<<gemm_blocks, 256>>>(W2);
    k_agg2<<<agg_blocks, 256>>>(b2, out);
}